// round 7
// baseline (speedup 1.0000x reference)
#include <cuda_runtime.h>

// GAE backward scan, round 7: R5 structure (reset kernel + atomic flags) with
// float4 (LDG.128/STG.128) streams.
// adv[t] = delta[t] + GL*adv[t+1],  delta[t] = r[t] + GAMMA*v[t+1] - v[t]
// 64 time-chunks x 64 column-groups = 4096 blocks; each thread owns 4 adjacent
// columns. RMAX=16 keeps local[] = 64 regs (no spill). Truncated lookback
// DEPTH=12: gl^(16*12) ~ 7.7e-6 << 1e-3 tolerance; scratch stays L2-resident.

#define B_COLS 32768
#define TM1 1023            // output rows t = 0 .. 1022
#define GAMMA 0.99f
#define GL (0.99f * 0.95f)
#define NCHUNK 64
#define RMAX 16             // rows per chunk (last chunk: 15 valid)
#define GBLK 64             // column groups of 512 columns (B_COLS / 512)
#define DEPTH 12            // gl^(16*12) ~ 7.7e-6

__device__ float g_scratch[NCHUNK * B_COLS];  // C_k per (chunk, column)
__device__ int   g_flags[NCHUNK * GBLK];      // publish flags
__device__ int   g_ticket;                    // ordered tile assignment

__global__ void reset_kernel() {
    int i = blockIdx.x * blockDim.x + threadIdx.x;
    if (i < NCHUNK * GBLK) g_flags[i] = 0;
    if (i == 0) g_ticket = 0;
}

__global__ __launch_bounds__(128) void gae_chunk_kernel(
    const float* __restrict__ rewards,
    const float* __restrict__ values,
    float* __restrict__ out)
{
    __shared__ int s_ticket;
    if (threadIdx.x == 0) s_ticket = atomicAdd(&g_ticket, 1);
    __syncthreads();
    const int ticket = s_ticket;
    const int k  = ticket >> 6;          // chunk index 0..63 (0 = highest t)
    const int gx = ticket & (GBLK - 1);  // column group
    const int c4 = gx * 128 + threadIdx.x;   // float4 column index (0..8191)
    const int ROW4 = B_COLS / 4;             // row stride in float4 units
    const int t_hi = (TM1 - 1) - RMAX * k;   // 1022 - 16k

    const float4* r = (const float4*)rewards + c4;
    const float4* v = (const float4*)values + c4;
    float4* o = (float4*)out + c4;

    // ---- local backward scan (carry-in = 0), 16 rows, batched LDG.128 ----
    float4 local[RMAX];
    float ax = 0.0f, ay = 0.0f, az = 0.0f, aw = 0.0f;
    float4 vn = __ldcs(v + (t_hi + 1) * ROW4);

    if (k < NCHUNK - 1) {
        // Fast path: all rows valid, predicate-free.
        #pragma unroll
        for (int g0 = 0; g0 < RMAX; g0 += 4) {
            float4 rt[4], vt[4];
            #pragma unroll
            for (int i = 0; i < 4; ++i) {
                const int t = t_hi - (g0 + i);
                rt[i] = __ldcs(r + t * ROW4);
                vt[i] = __ldcs(v + t * ROW4);
            }
            #pragma unroll
            for (int i = 0; i < 4; ++i) {
                const float dx = fmaf(GAMMA, vn.x, rt[i].x) - vt[i].x;
                const float dy = fmaf(GAMMA, vn.y, rt[i].y) - vt[i].y;
                const float dz = fmaf(GAMMA, vn.z, rt[i].z) - vt[i].z;
                const float dw = fmaf(GAMMA, vn.w, rt[i].w) - vt[i].w;
                ax = fmaf(GL, ax, dx);
                ay = fmaf(GL, ay, dy);
                az = fmaf(GL, az, dz);
                aw = fmaf(GL, aw, dw);
                local[g0 + i] = make_float4(ax, ay, az, aw);
                vn = vt[i];
            }
        }
        // publish chunk-sum C_k
        *(float4*)&g_scratch[k * B_COLS + 4 * c4] = local[RMAX - 1];
        __threadfence();
        __syncthreads();
        if (threadIdx.x == 0) atomicExch(&g_flags[k * GBLK + gx], 1);
    } else {
        // Last chunk (k=63): t = 14..0; row index 15 invalid. No consumers.
        #pragma unroll
        for (int g0 = 0; g0 < RMAX; g0 += 4) {
            float4 rt[4], vt[4];
            #pragma unroll
            for (int i = 0; i < 4; ++i) {
                const int t = t_hi - (g0 + i);
                if (t >= 0) {
                    rt[i] = __ldcs(r + t * ROW4);
                    vt[i] = __ldcs(v + t * ROW4);
                } else {
                    rt[i] = make_float4(0.f, 0.f, 0.f, 0.f);
                    vt[i] = make_float4(0.f, 0.f, 0.f, 0.f);
                }
            }
            #pragma unroll
            for (int i = 0; i < 4; ++i) {
                const float dx = fmaf(GAMMA, vn.x, rt[i].x) - vt[i].x;
                const float dy = fmaf(GAMMA, vn.y, rt[i].y) - vt[i].y;
                const float dz = fmaf(GAMMA, vn.z, rt[i].z) - vt[i].z;
                const float dw = fmaf(GAMMA, vn.w, rt[i].w) - vt[i].w;
                ax = fmaf(GL, ax, dx);
                ay = fmaf(GL, ay, dy);
                az = fmaf(GL, az, dz);
                aw = fmaf(GL, aw, dw);
                local[g0 + i] = make_float4(ax, ay, az, aw);
                vn = vt[i];
            }
        }
    }

    // ---- truncated lookback: A = sum_{j=k-1 .. k-d} C_j * gl^(16*(k-1-j)) ----
    float Ax = 0.f, Ay = 0.f, Az = 0.f, Aw = 0.f;
    if (k > 0) {
        const int d = (k < DEPTH) ? k : DEPTH;
        if (threadIdx.x < d) {  // thread i waits on predecessor (k-1-i)
            while (atomicAdd(&g_flags[(k - 1 - (int)threadIdx.x) * GBLK + gx], 0) == 0) {}
        }
        __syncthreads();

        // gl^16 via 4 squarings
        const float g2 = GL * GL, g4 = g2 * g2, g8 = g4 * g4, gl16 = g8 * g8;

        float w = 1.0f;
        for (int j = k - 1; j >= k - d; --j) {
            const float4 Cj = *(const float4*)&g_scratch[j * B_COLS + 4 * c4];
            Ax = fmaf(Cj.x, w, Ax);
            Ay = fmaf(Cj.y, w, Ay);
            Az = fmaf(Cj.z, w, Az);
            Aw = fmaf(Cj.w, w, Aw);
            w *= gl16;
        }
    }

    // ---- fixup + store: adv[t_hi - i] = local[i] + A * gl^(i+1) ----
    if (k < NCHUNK - 1) {
        #pragma unroll
        for (int i = 0; i < RMAX; ++i) {
            Ax *= GL; Ay *= GL; Az *= GL; Aw *= GL;
            __stcs(o + (t_hi - i) * ROW4,
                   make_float4(local[i].x + Ax, local[i].y + Ay,
                               local[i].z + Az, local[i].w + Aw));
        }
    } else {
        #pragma unroll
        for (int i = 0; i < RMAX; ++i) {
            const int t = t_hi - i;
            Ax *= GL; Ay *= GL; Az *= GL; Aw *= GL;
            if (t >= 0)
                __stcs(o + t * ROW4,
                       make_float4(local[i].x + Ax, local[i].y + Ay,
                                   local[i].z + Az, local[i].w + Aw));
        }
    }
}

extern "C" void kernel_launch(void* const* d_in, const int* in_sizes, int n_in,
                              void* d_out, int out_size) {
    const float* rewards = (const float*)d_in[0];
    const float* values  = (const float*)d_in[1];
    float* out = (float*)d_out;

    reset_kernel<<<32, 128>>>();
    gae_chunk_kernel<<<NCHUNK * GBLK, 128>>>(rewards, values, out);
}

// round 8
// speedup vs baseline: 1.0527x; 1.0527x over previous
#include <cuda_runtime.h>

// GAE backward scan, round 8: R5's best kernel (float2, NCHUNK=32, truncated
// lookback) made single-graph-node via monotonic epoch flags — no reset kernel,
// no inline-asm polling (R6's regression source).
// adv[t] = delta[t] + GL*adv[t+1],  delta[t] = r[t] + GAMMA*v[t+1] - v[t]
// Publisher of launch E writes E+1 to its flag; consumers poll for >= E+1 with
// plain atomicAdd (R5-proven). Epoch = ticket >> 12 (grid is exactly 4096,
// replays are stream-serialized, flags monotone across replays).

#define B_COLS 32768
#define TM1 1023            // output rows t = 0 .. 1022
#define GAMMA 0.99f
#define GL (0.99f * 0.95f)
#define NCHUNK 32
#define RMAX 32             // rows per chunk (last chunk: 31 valid)
#define GBLK 128            // column groups of 256 columns (B_COLS / 256)
#define NBLK (NCHUNK * GBLK)   // 4096
#define DEPTH 6             // gl^(32*6) ~ 7.7e-6 << 1e-3 tolerance

__device__ float g_scratch[NCHUNK * B_COLS];   // C_k per (chunk, column)
__device__ unsigned int g_flags[NCHUNK * GBLK]; // epoch-stamped flags (zero-init)
__device__ unsigned int g_ticket;               // monotonic across replays

__global__ __launch_bounds__(128) void gae_chunk_kernel(
    const float* __restrict__ rewards,
    const float* __restrict__ values,
    float* __restrict__ out)
{
    __shared__ unsigned int s_ticket;
    if (threadIdx.x == 0) s_ticket = atomicAdd(&g_ticket, 1u);
    __syncthreads();
    const unsigned int ticket = s_ticket;
    const unsigned int want = (ticket >> 12) + 1u;   // epoch + 1
    const unsigned int lt = ticket & (NBLK - 1);
    const int k  = (int)(lt >> 7);          // chunk index 0..31 (0 = highest t)
    const int gx = (int)(lt & (GBLK - 1));  // column group
    const int c2 = gx * 128 + threadIdx.x;  // float2 column index (0..16383)
    const int ROW2 = B_COLS / 2;            // row stride in float2 units
    const int t_hi = (TM1 - 1) - RMAX * k;  // 1022 - 32k

    const float2* r = (const float2*)rewards + c2;
    const float2* v = (const float2*)values + c2;
    float2* o = (float2*)out + c2;

    // ---- local backward scan (carry-in = 0), 32 rows, batched LDG.64 ----
    float2 local[RMAX];
    float ax = 0.0f, ay = 0.0f;
    float2 vn = __ldcs(v + (t_hi + 1) * ROW2);

    if (k < NCHUNK - 1) {
        // Fast path: all rows valid, no predication.
        #pragma unroll
        for (int g0 = 0; g0 < RMAX; g0 += 8) {
            float2 rt[8], vt[8];
            #pragma unroll
            for (int i = 0; i < 8; ++i) {
                const int t = t_hi - (g0 + i);
                rt[i] = __ldcs(r + t * ROW2);
                vt[i] = __ldcs(v + t * ROW2);
            }
            #pragma unroll
            for (int i = 0; i < 8; ++i) {
                const float dx = fmaf(GAMMA, vn.x, rt[i].x) - vt[i].x;
                const float dy = fmaf(GAMMA, vn.y, rt[i].y) - vt[i].y;
                ax = fmaf(GL, ax, dx);
                ay = fmaf(GL, ay, dy);
                local[g0 + i] = make_float2(ax, ay);
                vn = vt[i];
            }
        }
        // publish chunk-sum C_k with epoch stamp
        *(float2*)&g_scratch[k * B_COLS + 2 * c2] = local[RMAX - 1];
        __threadfence();
        __syncthreads();
        if (threadIdx.x == 0) atomicExch(&g_flags[k * GBLK + gx], want);
    } else {
        // Last chunk (k=31): t goes 30..0; row index 31 invalid. No consumers.
        #pragma unroll
        for (int g0 = 0; g0 < RMAX; g0 += 8) {
            float2 rt[8], vt[8];
            #pragma unroll
            for (int i = 0; i < 8; ++i) {
                const int t = t_hi - (g0 + i);
                if (t >= 0) {
                    rt[i] = __ldcs(r + t * ROW2);
                    vt[i] = __ldcs(v + t * ROW2);
                } else {
                    rt[i] = make_float2(0.0f, 0.0f);
                    vt[i] = make_float2(0.0f, 0.0f);
                }
            }
            #pragma unroll
            for (int i = 0; i < 8; ++i) {
                const float dx = fmaf(GAMMA, vn.x, rt[i].x) - vt[i].x;
                const float dy = fmaf(GAMMA, vn.y, rt[i].y) - vt[i].y;
                ax = fmaf(GL, ax, dx);
                ay = fmaf(GL, ay, dy);
                local[g0 + i] = make_float2(ax, ay);
                vn = vt[i];
            }
        }
    }

    // ---- truncated lookback: A = sum_{j=k-1 .. k-d} C_j * gl^(32*(k-1-j)) ----
    float Ax = 0.0f, Ay = 0.0f;
    if (k > 0) {
        const int d = (k < DEPTH) ? k : DEPTH;
        if (threadIdx.x < (unsigned)d) {  // thread i waits on predecessor (k-1-i)
            unsigned int* fp = &g_flags[(k - 1 - (int)threadIdx.x) * GBLK + gx];
            while (atomicAdd(fp, 0u) < want) {}
        }
        __syncthreads();

        // gl^32 via 5 squarings
        const float g2 = GL * GL, g4 = g2 * g2, g8 = g4 * g4;
        const float g16 = g8 * g8, gl32 = g16 * g16;

        float w = 1.0f;
        for (int j = k - 1; j >= k - d; --j) {
            const float2 Cj = *(const float2*)&g_scratch[j * B_COLS + 2 * c2];
            Ax = fmaf(Cj.x, w, Ax);
            Ay = fmaf(Cj.y, w, Ay);
            w *= gl32;
        }
    }

    // ---- fixup + store: adv[t_hi - i] = local[i] + A * gl^(i+1) ----
    if (k < NCHUNK - 1) {
        #pragma unroll
        for (int i = 0; i < RMAX; ++i) {
            Ax *= GL;
            Ay *= GL;
            __stcs(o + (t_hi - i) * ROW2,
                   make_float2(local[i].x + Ax, local[i].y + Ay));
        }
    } else {
        #pragma unroll
        for (int i = 0; i < RMAX; ++i) {
            const int t = t_hi - i;
            Ax *= GL;
            Ay *= GL;
            if (t >= 0)
                __stcs(o + t * ROW2,
                       make_float2(local[i].x + Ax, local[i].y + Ay));
        }
    }
}

extern "C" void kernel_launch(void* const* d_in, const int* in_sizes, int n_in,
                              void* d_out, int out_size) {
    const float* rewards = (const float*)d_in[0];
    const float* values  = (const float*)d_in[1];
    float* out = (float*)d_out;

    gae_chunk_kernel<<<NBLK, 128>>>(rewards, values, out);
}

// round 9
// speedup vs baseline: 1.0750x; 1.0212x over previous
#include <cuda_runtime.h>

// GAE backward scan, round 9: R8 single-node epoch design + forced 5 blocks/SM
// via __launch_bounds__(128, 5) (caps regs at 102 = R5's natural allocation,
// which fit this body without spills). Epoch machinery cost 12 regs -> 4
// blocks/SM in R6/R8; this reclaims R5's occupancy while keeping the graph to
// one node (~3.5us less replay overhead than the two-node version).
// adv[t] = delta[t] + GL*adv[t+1],  delta[t] = r[t] + GAMMA*v[t+1] - v[t]

#define B_COLS 32768
#define TM1 1023            // output rows t = 0 .. 1022
#define GAMMA 0.99f
#define GL (0.99f * 0.95f)
#define NCHUNK 32
#define RMAX 32             // rows per chunk (last chunk: 31 valid)
#define GBLK 128            // column groups of 256 columns (B_COLS / 256)
#define NBLK (NCHUNK * GBLK)   // 4096
#define DEPTH 6             // gl^(32*6) ~ 7.7e-6 << 1e-3 tolerance

__device__ float g_scratch[NCHUNK * B_COLS];    // C_k per (chunk, column)
__device__ unsigned int g_flags[NCHUNK * GBLK]; // epoch-stamped flags (zero-init)
__device__ unsigned int g_ticket;               // monotonic across replays

__global__ __launch_bounds__(128, 5) void gae_chunk_kernel(
    const float* __restrict__ rewards,
    const float* __restrict__ values,
    float* __restrict__ out)
{
    __shared__ unsigned int s_ticket;
    if (threadIdx.x == 0) s_ticket = atomicAdd(&g_ticket, 1u);
    __syncthreads();
    const unsigned int ticket = s_ticket;
    const unsigned int want = (ticket >> 12) + 1u;   // epoch + 1
    const unsigned int lt = ticket & (NBLK - 1);
    const int k  = (int)(lt >> 7);          // chunk index 0..31 (0 = highest t)
    const int gx = (int)(lt & (GBLK - 1));  // column group
    const int c2 = gx * 128 + threadIdx.x;  // float2 column index (0..16383)
    const int ROW2 = B_COLS / 2;            // row stride in float2 units
    const int t_hi = (TM1 - 1) - RMAX * k;  // 1022 - 32k

    const float2* r = (const float2*)rewards + c2;
    const float2* v = (const float2*)values + c2;
    float2* o = (float2*)out + c2;

    // ---- local backward scan (carry-in = 0), 32 rows, batched LDG.64 ----
    float2 local[RMAX];
    float ax = 0.0f, ay = 0.0f;
    float2 vn = __ldcs(v + (t_hi + 1) * ROW2);

    if (k < NCHUNK - 1) {
        // Fast path: all rows valid, no predication.
        #pragma unroll
        for (int g0 = 0; g0 < RMAX; g0 += 8) {
            float2 rt[8], vt[8];
            #pragma unroll
            for (int i = 0; i < 8; ++i) {
                const int t = t_hi - (g0 + i);
                rt[i] = __ldcs(r + t * ROW2);
                vt[i] = __ldcs(v + t * ROW2);
            }
            #pragma unroll
            for (int i = 0; i < 8; ++i) {
                const float dx = fmaf(GAMMA, vn.x, rt[i].x) - vt[i].x;
                const float dy = fmaf(GAMMA, vn.y, rt[i].y) - vt[i].y;
                ax = fmaf(GL, ax, dx);
                ay = fmaf(GL, ay, dy);
                local[g0 + i] = make_float2(ax, ay);
                vn = vt[i];
            }
        }
        // publish chunk-sum C_k with epoch stamp
        *(float2*)&g_scratch[k * B_COLS + 2 * c2] = local[RMAX - 1];
        __threadfence();
        __syncthreads();
        if (threadIdx.x == 0) atomicExch(&g_flags[k * GBLK + gx], want);
    } else {
        // Last chunk (k=31): t goes 30..0; row index 31 invalid. No consumers.
        #pragma unroll
        for (int g0 = 0; g0 < RMAX; g0 += 8) {
            float2 rt[8], vt[8];
            #pragma unroll
            for (int i = 0; i < 8; ++i) {
                const int t = t_hi - (g0 + i);
                if (t >= 0) {
                    rt[i] = __ldcs(r + t * ROW2);
                    vt[i] = __ldcs(v + t * ROW2);
                } else {
                    rt[i] = make_float2(0.0f, 0.0f);
                    vt[i] = make_float2(0.0f, 0.0f);
                }
            }
            #pragma unroll
            for (int i = 0; i < 8; ++i) {
                const float dx = fmaf(GAMMA, vn.x, rt[i].x) - vt[i].x;
                const float dy = fmaf(GAMMA, vn.y, rt[i].y) - vt[i].y;
                ax = fmaf(GL, ax, dx);
                ay = fmaf(GL, ay, dy);
                local[g0 + i] = make_float2(ax, ay);
                vn = vt[i];
            }
        }
    }

    // ---- truncated lookback: A = sum_{j=k-1 .. k-d} C_j * gl^(32*(k-1-j)) ----
    float Ax = 0.0f, Ay = 0.0f;
    if (k > 0) {
        const int d = (k < DEPTH) ? k : DEPTH;
        if (threadIdx.x < (unsigned)d) {  // thread i waits on predecessor (k-1-i)
            unsigned int* fp = &g_flags[(k - 1 - (int)threadIdx.x) * GBLK + gx];
            while (atomicAdd(fp, 0u) < want) {}
        }
        __syncthreads();

        // gl^32 via 5 squarings
        const float g2 = GL * GL, g4 = g2 * g2, g8 = g4 * g4;
        const float g16 = g8 * g8, gl32 = g16 * g16;

        float w = 1.0f;
        for (int j = k - 1; j >= k - d; --j) {
            const float2 Cj = *(const float2*)&g_scratch[j * B_COLS + 2 * c2];
            Ax = fmaf(Cj.x, w, Ax);
            Ay = fmaf(Cj.y, w, Ay);
            w *= gl32;
        }
    }

    // ---- fixup + store: adv[t_hi - i] = local[i] + A * gl^(i+1) ----
    if (k < NCHUNK - 1) {
        #pragma unroll
        for (int i = 0; i < RMAX; ++i) {
            Ax *= GL;
            Ay *= GL;
            __stcs(o + (t_hi - i) * ROW2,
                   make_float2(local[i].x + Ax, local[i].y + Ay));
        }
    } else {
        #pragma unroll
        for (int i = 0; i < RMAX; ++i) {
            const int t = t_hi - i;
            Ax *= GL;
            Ay *= GL;
            if (t >= 0)
                __stcs(o + t * ROW2,
                       make_float2(local[i].x + Ax, local[i].y + Ay));
        }
    }
}

extern "C" void kernel_launch(void* const* d_in, const int* in_sizes, int n_in,
                              void* d_out, int out_size) {
    const float* rewards = (const float*)d_in[0];
    const float* values  = (const float*)d_in[1];
    float* out = (float*)d_out;

    gae_chunk_kernel<<<NBLK, 128>>>(rewards, values, out);
}